// round 1
// baseline (speedup 1.0000x reference)
#include <cuda_runtime.h>
#include <cuda_bf16.h>

#define GRID_N   128
#define GRID_MASK 127
#define NUM_CELLS (GRID_N * GRID_N * GRID_N)
#define D_FEAT   8
#define N_POINTS 1000000

// Grid scratch: [NUM_CELLS][8 floats] = 2 float4 per cell = 64 MB.
__device__ float4 g_grid[NUM_CELLS * 2];

__global__ __launch_bounds__(256)
void p2g_kernel(const float* __restrict__ pos,
                const float4* __restrict__ feat4,
                int n) {
    int i = blockIdx.x * blockDim.x + threadIdx.x;
    if (i >= n) return;

    float px = pos[3 * i + 0];
    float py = pos[3 * i + 1];
    float pz = pos[3 * i + 2];

    float rx = px * (float)GRID_N;
    float ry = py * (float)GRID_N;
    float rz = pz * (float)GRID_N;
    int bx = (int)floorf(rx);
    int by = (int)floorf(ry);
    int bz = (int)floorf(rz);
    float fx = rx - (float)bx;
    float fy = ry - (float)by;
    float fz = rz - (float)bz;

    float wx[2] = {1.0f - fx, fx};
    float wy[2] = {1.0f - fy, fy};
    float wz[2] = {1.0f - fz, fz};

    float4 f0 = feat4[2 * i + 0];
    float4 f1 = feat4[2 * i + 1];

    #pragma unroll
    for (int ox = 0; ox < 2; ox++) {
        int nx = (bx + ox) & GRID_MASK;
        #pragma unroll
        for (int oy = 0; oy < 2; oy++) {
            int ny = (by + oy) & GRID_MASK;
            float wxy = wx[ox] * wy[oy];
            #pragma unroll
            for (int oz = 0; oz < 2; oz++) {
                int nz = (bz + oz) & GRID_MASK;
                float w = wxy * wz[oz];
                int hid = ((nx << 7) + ny) * GRID_N + nz;
                float4 c0 = make_float4(w * f0.x, w * f0.y, w * f0.z, w * f0.w);
                float4 c1 = make_float4(w * f1.x, w * f1.y, w * f1.z, w * f1.w);
                atomicAdd(&g_grid[2 * hid + 0], c0);
                atomicAdd(&g_grid[2 * hid + 1], c1);
            }
        }
    }
}

__global__ __launch_bounds__(256)
void g2p_kernel(const float* __restrict__ pos,
                float4* __restrict__ out4,
                int n) {
    int i = blockIdx.x * blockDim.x + threadIdx.x;
    if (i >= n) return;

    float px = pos[3 * i + 0];
    float py = pos[3 * i + 1];
    float pz = pos[3 * i + 2];

    float rx = px * (float)GRID_N;
    float ry = py * (float)GRID_N;
    float rz = pz * (float)GRID_N;
    int bx = (int)floorf(rx);
    int by = (int)floorf(ry);
    int bz = (int)floorf(rz);
    float fx = rx - (float)bx;
    float fy = ry - (float)by;
    float fz = rz - (float)bz;

    float wx[2] = {1.0f - fx, fx};
    float wy[2] = {1.0f - fy, fy};
    float wz[2] = {1.0f - fz, fz};

    float4 acc0 = make_float4(0.f, 0.f, 0.f, 0.f);
    float4 acc1 = make_float4(0.f, 0.f, 0.f, 0.f);

    #pragma unroll
    for (int ox = 0; ox < 2; ox++) {
        int nx = (bx + ox) & GRID_MASK;
        #pragma unroll
        for (int oy = 0; oy < 2; oy++) {
            int ny = (by + oy) & GRID_MASK;
            float wxy = wx[ox] * wy[oy];
            #pragma unroll
            for (int oz = 0; oz < 2; oz++) {
                int nz = (bz + oz) & GRID_MASK;
                float w = wxy * wz[oz];
                int hid = ((nx << 7) + ny) * GRID_N + nz;
                float4 g0 = g_grid[2 * hid + 0];
                float4 g1 = g_grid[2 * hid + 1];
                acc0.x += w * g0.x; acc0.y += w * g0.y;
                acc0.z += w * g0.z; acc0.w += w * g0.w;
                acc1.x += w * g1.x; acc1.y += w * g1.y;
                acc1.z += w * g1.z; acc1.w += w * g1.w;
            }
        }
    }

    out4[2 * i + 0] = acc0;
    out4[2 * i + 1] = acc1;
}

extern "C" void kernel_launch(void* const* d_in, const int* in_sizes, int n_in,
                              void* d_out, int out_size) {
    const float* pos  = (const float*)d_in[0];   // [N,3] f32
    const float* feat = (const float*)d_in[1];   // [N,8] f32
    float* out        = (float*)d_out;           // [N,8] f32
    int n = in_sizes[0] / 3;

    void* gptr = nullptr;
    cudaGetSymbolAddress(&gptr, g_grid);
    cudaMemsetAsync(gptr, 0, (size_t)NUM_CELLS * 2 * sizeof(float4), 0);

    int threads = 256;
    int blocks = (n + threads - 1) / threads;
    p2g_kernel<<<blocks, threads>>>(pos, (const float4*)feat, n);
    g2p_kernel<<<blocks, threads>>>(pos, (float4*)out, n);
}